// round 1
// baseline (speedup 1.0000x reference)
#include <cuda_runtime.h>
#include <math.h>

#define D      256
#define ATOM   118
#define K_TOT  121   // 118 atom dims + 3 coord dims, fused
#define OUTD   100
#define MAXN   50000
#define MAXG   500

// Scratch (allocation-free rule: __device__ globals)
__device__ float g_Wc[K_TOT * D];          // fused input->hidden weight [121][256]
__device__ float g_bh[D];                  // fused bias
__device__ float g_h[MAXN * D];            // node embeddings (gather source)
__device__ float g_acc[MAXN * D];          // (1+eps)*h + scatter-sum target
__device__ float g_pooled[MAXG * D];       // per-graph sums

__device__ __forceinline__ void red_add_f4(float4* addr, float4 v) {
    asm volatile("red.global.add.v4.f32 [%0], {%1,%2,%3,%4};"
                 :: "l"(addr), "f"(v.x), "f"(v.y), "f"(v.z), "f"(v.w) : "memory");
}

// ---------------------------------------------------------------------------
// Precompute fused weights: Wc[k][d] = sum_j Win[k][j] * W_node[(off+j)][d]
// ---------------------------------------------------------------------------
__global__ void k_prep_w(const float* __restrict__ W_atom,
                         const float* __restrict__ W_coord,
                         const float* __restrict__ W_node) {
    int k = blockIdx.x;      // 0..120
    int d = threadIdx.x;     // 0..255
    float s = 0.f;
    if (k < ATOM) {
        const float* wa = W_atom + (size_t)k * D;
        #pragma unroll 4
        for (int j = 0; j < D; j++) s += wa[j] * W_node[(size_t)j * D + d];
    } else {
        const float* wcrd = W_coord + (size_t)(k - ATOM) * D;
        #pragma unroll 4
        for (int j = 0; j < D; j++) s += wcrd[j] * W_node[(size_t)(D + j) * D + d];
    }
    g_Wc[k * D + d] = s;
}

__global__ void k_prep_bh(const float* __restrict__ b_atom,
                          const float* __restrict__ b_coord,
                          const float* __restrict__ b_node,
                          const float* __restrict__ W_node) {
    int d = threadIdx.x;
    float s = b_node[d];
    #pragma unroll 4
    for (int j = 0; j < D; j++) {
        s += b_atom[j]  * W_node[(size_t)j * D + d];
        s += b_coord[j] * W_node[(size_t)(D + j) * D + d];
    }
    g_bh[d] = s;
}

__global__ void k_zero_pooled(int n) {
    int i = blockIdx.x * blockDim.x + threadIdx.x;
    if (i < n) g_pooled[i] = 0.f;
}

// ---------------------------------------------------------------------------
// Node embedding GEMM: h[n][d] = sum_k A[n][k]*Wc[k][d] + bh[d]
// A = [atomic_num | coord], K=121. Block = 64 nodes x 256 dims, thread = 8x8.
// Also writes acc = (1+eps)*h.
// ---------------------------------------------------------------------------
__global__ void __launch_bounds__(256) k_node_embed(
    const float* __restrict__ atom, const float* __restrict__ coord,
    const float* __restrict__ eps_gnn, int N)
{
    __shared__ float As[64 * 124];   // 64 nodes x K (padded 121->124)
    const int n0  = blockIdx.x * 64;
    const int tid = threadIdx.x;

    // Stage A tile (zero-pad missing nodes / K slots)
    for (int idx = tid; idx < 64 * K_TOT; idx += 256) {
        int i = idx / K_TOT;
        int k = idx - i * K_TOT;
        int n = n0 + i;
        float v = 0.f;
        if (n < N)
            v = (k < ATOM) ? atom[(size_t)n * ATOM + k]
                           : coord[(size_t)n * 3 + (k - ATOM)];
        As[i * 124 + k] = v;
    }
    __syncthreads();

    const int dg = tid & 31;   // dim group: dims dg*8 .. dg*8+7
    const int ng = tid >> 5;   // node group: nodes ng*8 .. ng*8+7

    float acc[8][8];
    #pragma unroll
    for (int i = 0; i < 8; i++)
        #pragma unroll
        for (int j = 0; j < 8; j++) acc[i][j] = 0.f;

    const float* wc = g_Wc + dg * 8;
    for (int k = 0; k < K_TOT; k++) {
        float4 b0 = *(const float4*)(wc + (size_t)k * D);
        float4 b1 = *(const float4*)(wc + (size_t)k * D + 4);
        float a[8];
        #pragma unroll
        for (int i = 0; i < 8; i++) a[i] = As[(ng * 8 + i) * 124 + k];
        #pragma unroll
        for (int i = 0; i < 8; i++) {
            acc[i][0] += a[i] * b0.x; acc[i][1] += a[i] * b0.y;
            acc[i][2] += a[i] * b0.z; acc[i][3] += a[i] * b0.w;
            acc[i][4] += a[i] * b1.x; acc[i][5] += a[i] * b1.y;
            acc[i][6] += a[i] * b1.z; acc[i][7] += a[i] * b1.w;
        }
    }

    const float eps1 = 1.f + eps_gnn[0];
    float4 bh0 = *(const float4*)(g_bh + dg * 8);
    float4 bh1 = *(const float4*)(g_bh + dg * 8 + 4);

    #pragma unroll
    for (int i = 0; i < 8; i++) {
        int n = n0 + ng * 8 + i;
        if (n < N) {
            float4 o0, o1;
            o0.x = acc[i][0] + bh0.x; o0.y = acc[i][1] + bh0.y;
            o0.z = acc[i][2] + bh0.z; o0.w = acc[i][3] + bh0.w;
            o1.x = acc[i][4] + bh1.x; o1.y = acc[i][5] + bh1.y;
            o1.z = acc[i][6] + bh1.z; o1.w = acc[i][7] + bh1.w;
            float* hp = g_h   + (size_t)n * D + dg * 8;
            float* ap = g_acc + (size_t)n * D + dg * 8;
            *(float4*)(hp)     = o0;
            *(float4*)(hp + 4) = o1;
            float4 s0, s1;
            s0.x = eps1 * o0.x; s0.y = eps1 * o0.y; s0.z = eps1 * o0.z; s0.w = eps1 * o0.w;
            s1.x = eps1 * o1.x; s1.y = eps1 * o1.y; s1.z = eps1 * o1.z; s1.w = eps1 * o1.w;
            *(float4*)(ap)     = s0;
            *(float4*)(ap + 4) = s1;
        }
    }
}

// ---------------------------------------------------------------------------
// Edge scatter: acc[dst] += h[src].  64 threads/edge, one float4 each.
// h and acc are L2-resident (51.2 MB each).
// ---------------------------------------------------------------------------
__global__ void __launch_bounds__(256) k_edges(const int* __restrict__ src,
                                               const int* __restrict__ dst, int E) {
    int e = (blockIdx.x << 2) + (threadIdx.x >> 6);
    if (e >= E) return;
    int t = threadIdx.x & 63;
    int s = __ldg(src + e);
    int d = __ldg(dst + e);
    float4 v = *((const float4*)(g_h + (size_t)s * D) + t);
    red_add_f4((float4*)(g_acc + (size_t)d * D) + t, v);
}

// ---------------------------------------------------------------------------
// Pool: pooled[graph_id[n]] += acc[n] for masked nodes
// ---------------------------------------------------------------------------
__global__ void __launch_bounds__(256) k_pool(const int* __restrict__ graph_id,
                                              const int* __restrict__ abs_mask, int N) {
    int n = (blockIdx.x << 2) + (threadIdx.x >> 6);
    if (n >= N) return;
    if (__ldg(abs_mask + n) == 0) return;
    int t = threadIdx.x & 63;
    int g = __ldg(graph_id + n);
    float4 v = *((const float4*)(g_acc + (size_t)n * D) + t);
    red_add_f4((float4*)(g_pooled + (size_t)g * D) + t, v);
}

// ---------------------------------------------------------------------------
// MLP + sigmoid: out[g][o] = sigmoid(b[o] + sum_d pooled[g][d]/N * W[d][o])
// ---------------------------------------------------------------------------
__global__ void k_mlp(const float* __restrict__ W_mlp, const float* __restrict__ b_mlp,
                      float* __restrict__ out, float invN) {
    __shared__ float p[D];
    int g = blockIdx.x;
    int tid = threadIdx.x;   // 128
    for (int i = tid; i < D; i += 128) p[i] = g_pooled[(size_t)g * D + i] * invN;
    __syncthreads();
    if (tid < OUTD) {
        float z = b_mlp[tid];
        #pragma unroll 4
        for (int d = 0; d < D; d++) z += p[d] * W_mlp[(size_t)d * OUTD + tid];
        out[(size_t)g * OUTD + tid] = 1.f / (1.f + __expf(-z));
    }
}

// ---------------------------------------------------------------------------
extern "C" void kernel_launch(void* const* d_in, const int* in_sizes, int n_in,
                              void* d_out, int out_size) {
    const float* atomic_num = (const float*)d_in[0];
    const float* coord      = (const float*)d_in[1];
    // d_in[2] = radius : dead (edge weight is identically 1 in reference)
    const int*   src        = (const int*)d_in[3];
    const int*   dst        = (const int*)d_in[4];
    const int*   graph_id   = (const int*)d_in[5];
    const int*   abs_mask   = (const int*)d_in[6];
    const float* W_atom     = (const float*)d_in[7];
    const float* b_atom     = (const float*)d_in[8];
    const float* W_coord    = (const float*)d_in[9];
    const float* b_coord    = (const float*)d_in[10];
    const float* W_node     = (const float*)d_in[11];
    const float* b_node     = (const float*)d_in[12];
    // d_in[13] = exp_gnn : dead in forward math
    const float* eps_gnn    = (const float*)d_in[14];
    const float* W_mlp      = (const float*)d_in[15];
    const float* b_mlp      = (const float*)d_in[16];
    float* out = (float*)d_out;

    const int N = in_sizes[5];           // 50000 nodes
    const int E = in_sizes[3];           // 1.6M edges
    const int G = out_size / OUTD;       // 500 graphs

    k_prep_w<<<K_TOT, D>>>(W_atom, W_coord, W_node);
    k_prep_bh<<<1, D>>>(b_atom, b_coord, b_node, W_node);
    k_zero_pooled<<<(G * D + 255) / 256, 256>>>(G * D);
    k_node_embed<<<(N + 63) / 64, 256>>>(atomic_num, coord, eps_gnn, N);
    k_edges<<<(E + 3) / 4, 256>>>(src, dst, E);
    k_pool<<<(N + 3) / 4, 256>>>(graph_id, abs_mask, N);
    k_mlp<<<G, 128>>>(W_mlp, b_mlp, out, 1.f / (float)N);
}

// round 2
// speedup vs baseline: 2.3433x; 2.3433x over previous
#include <cuda_runtime.h>
#include <math.h>

#define OUTD   100
#define DDIM   256
#define ATOM   118
#define KTOT   122      // 118 atom + 3 coord + 1 constant (weight-sum feature)
#define MAXG   512
#define MAXE   2000000
#define BPG    4        // blocks per graph in accumulate

// __device__ scratch (allocation-free rule)
__device__ float g_P[512 * OUTD];          // W_node @ W_mlp
__device__ float g_Weff[KTOT * OUTD];      // fused [A-features+const] -> logits
__device__ float g_M[MAXG * 128];          // per-graph weighted feature sums (padded row 128)
__device__ int   g_hist[MAXG];
__device__ int   g_off[MAXG + 1];
__device__ int   g_cursor[MAXG];
__device__ int   g_ent[MAXE];              // entry = node index, sign bit => node-entry (weight 1+eps)

// ---------------------------------------------------------------------------
// P[j][o] = sum_d W_node[j][d] * W_mlp[d][o]     (512 x 100)
// ---------------------------------------------------------------------------
__global__ void kP(const float* __restrict__ Wn, const float* __restrict__ Wm) {
    int j = blockIdx.x, o = threadIdx.x;
    float s = 0.f;
    #pragma unroll 4
    for (int d = 0; d < DDIM; d++) s += Wn[j * DDIM + d] * Wm[d * OUTD + o];
    g_P[j * OUTD + o] = s;
}

// ---------------------------------------------------------------------------
// W_eff[k][o]:
//   k<118 : row k of W_atom  @ P_top
//   118-120: row of W_coord  @ P_bot
//   k=121 : b_node@W_mlp + b_atom@P_top + b_coord@P_bot   (the "bh" row)
// ---------------------------------------------------------------------------
__global__ void kWeff(const float* __restrict__ Wa, const float* __restrict__ Wc,
                      const float* __restrict__ ba, const float* __restrict__ bc,
                      const float* __restrict__ bn, const float* __restrict__ Wm) {
    int k = blockIdx.x, o = threadIdx.x;
    float s = 0.f;
    if (k < ATOM) {
        #pragma unroll 4
        for (int m = 0; m < DDIM; m++) s += Wa[k * DDIM + m] * g_P[m * OUTD + o];
    } else if (k < 121) {
        #pragma unroll 4
        for (int m = 0; m < DDIM; m++) s += Wc[(k - ATOM) * DDIM + m] * g_P[(DDIM + m) * OUTD + o];
    } else {
        #pragma unroll 4
        for (int d = 0; d < DDIM; d++) s += bn[d] * Wm[d * OUTD + o];
        #pragma unroll 4
        for (int m = 0; m < DDIM; m++)
            s += ba[m] * g_P[m * OUTD + o] + bc[m] * g_P[(DDIM + m) * OUTD + o];
    }
    g_Weff[k * OUTD + o] = s;
}

// ---------------------------------------------------------------------------
__global__ void k_zero(int G) {
    int i = blockIdx.x * 256 + threadIdx.x;
    if (i < G * 128) g_M[i] = 0.f;
    if (i < G) g_hist[i] = 0;
}

// ---------------------------------------------------------------------------
// Histogram of entries per graph. Index space [0, E+N):
//   i <  E : edge i  -> target node dst[i]
//   i >= E : node i-E -> itself
// Entry exists iff mask[target]; bin = graph_id[target].
// ---------------------------------------------------------------------------
__global__ void __launch_bounds__(256) k_hist(const int* __restrict__ dst,
                                              const int* __restrict__ gid,
                                              const int* __restrict__ mask,
                                              int E, int N, int G) {
    __shared__ int sh[MAXG];
    for (int t = threadIdx.x; t < G; t += 256) sh[t] = 0;
    __syncthreads();
    int total = E + N;
    for (int i = blockIdx.x * 256 + threadIdx.x; i < total; i += gridDim.x * 256) {
        int n = (i < E) ? __ldg(dst + i) : (i - E);
        if (__ldg(mask + n)) atomicAdd(&sh[__ldg(gid + n)], 1);
    }
    __syncthreads();
    for (int t = threadIdx.x; t < G; t += 256) if (sh[t]) atomicAdd(&g_hist[t], sh[t]);
}

// ---------------------------------------------------------------------------
// Exclusive scan over G<=512 bins (single block of 512)
// ---------------------------------------------------------------------------
__global__ void k_scan(int G) {
    __shared__ int ws[16];
    int t = threadIdx.x, lane = t & 31, w = t >> 5;
    int v = (t < G) ? g_hist[t] : 0;
    int x = v;
    #pragma unroll
    for (int o = 1; o < 32; o <<= 1) { int y = __shfl_up_sync(~0u, x, o); if (lane >= o) x += y; }
    if (lane == 31) ws[w] = x;
    __syncthreads();
    if (w == 0) {
        int y = (lane < 16) ? ws[lane] : 0;
        #pragma unroll
        for (int o = 1; o < 16; o <<= 1) { int z = __shfl_up_sync(~0u, y, o); if (lane >= o) y += z; }
        if (lane < 16) ws[lane] = y;
    }
    __syncthreads();
    int incl = x + (w > 0 ? ws[w - 1] : 0);
    if (t < G) { g_off[t + 1] = incl; g_cursor[t] = incl - v; }
    if (t == 0) g_off[0] = 0;
}

// ---------------------------------------------------------------------------
// Scatter entry node-ids into graph buckets. Node entries get sign bit set.
// ---------------------------------------------------------------------------
__global__ void __launch_bounds__(256) k_scatter(const int* __restrict__ src,
                                                 const int* __restrict__ dst,
                                                 const int* __restrict__ gid,
                                                 const int* __restrict__ mask,
                                                 int E, int N) {
    int total = E + N;
    for (int i = blockIdx.x * 256 + threadIdx.x; i < total; i += gridDim.x * 256) {
        if (i < E) {
            int d = __ldg(dst + i);
            if (__ldg(mask + d)) {
                int p = atomicAdd(&g_cursor[__ldg(gid + d)], 1);
                g_ent[p] = __ldg(src + i);
            }
        } else {
            int n = i - E;
            if (__ldg(mask + n)) {
                int p = atomicAdd(&g_cursor[__ldg(gid + n)], 1);
                g_ent[p] = n | 0x80000000;
            }
        }
    }
}

// ---------------------------------------------------------------------------
// M[g][k] = sum over entries of graph g:  w * A[node][k]
//   A[node] = [atomic_num(118) | coord(3) | 1.0]
// 32 warps per graph (BPG blocks x 8 warps); lane owns k = lane + 32*{0..3}.
// Register accumulate -> smem reduce -> one global atomic per (block,k).
// ---------------------------------------------------------------------------
__global__ void __launch_bounds__(256) k_accum(const float* __restrict__ atom,
                                               const float* __restrict__ coord,
                                               const float* __restrict__ eps) {
    int g    = blockIdx.x / BPG;
    int part = blockIdx.x % BPG;
    int lane = threadIdx.x & 31;
    int wid  = (part << 3) + (threadIdx.x >> 5);   // 0..31 within graph
    int off = g_off[g], end = g_off[g + 1];
    float wn = 1.f + __ldg(eps);

    float a0 = 0.f, a1 = 0.f, a2 = 0.f, a3 = 0.f;
    int i = off + wid;
    bool valid = i < end;
    int ent = valid ? g_ent[i] : 0;
    while (valid) {
        int ni = i + 32;
        bool nv = ni < end;
        int nent = nv ? g_ent[ni] : 0;          // prefetch next entry id

        int node = ent & 0x7FFFFFFF;
        float w = (ent < 0) ? wn : 1.f;
        const float* ar = atom + (size_t)node * ATOM;
        a0 += w * __ldg(ar + lane);
        a1 += w * __ldg(ar + lane + 32);
        a2 += w * __ldg(ar + lane + 64);
        int k3 = lane + 96;
        if (k3 < ATOM)       a3 += w * __ldg(ar + k3);
        else if (k3 < 121)   a3 += w * __ldg(coord + (size_t)node * 3 + (k3 - ATOM));
        else if (k3 == 121)  a3 += w;

        i = ni; ent = nent; valid = nv;
    }

    __shared__ float red[128];
    if (threadIdx.x < 128) red[threadIdx.x] = 0.f;
    __syncthreads();
    atomicAdd(&red[lane],      a0);
    atomicAdd(&red[lane + 32], a1);
    atomicAdd(&red[lane + 64], a2);
    atomicAdd(&red[lane + 96], a3);
    __syncthreads();
    if (threadIdx.x < KTOT) atomicAdd(&g_M[g * 128 + threadIdx.x], red[threadIdx.x]);
}

// ---------------------------------------------------------------------------
// out[g][o] = sigmoid( (M[g] @ W_eff)[o] / N + b_mlp[o] )
// ---------------------------------------------------------------------------
__global__ void __launch_bounds__(128) k_out(const float* __restrict__ bm,
                                             float* __restrict__ out, float invN) {
    __shared__ float sm[KTOT];
    int g = blockIdx.x, t = threadIdx.x;
    if (t < KTOT) sm[t] = g_M[g * 128 + t];
    __syncthreads();
    if (t < OUTD) {
        float z = 0.f;
        #pragma unroll 2
        for (int k = 0; k < KTOT; k++) z += sm[k] * g_Weff[k * OUTD + t];
        z = z * invN + bm[t];
        out[(size_t)g * OUTD + t] = 1.f / (1.f + __expf(-z));
    }
}

// ---------------------------------------------------------------------------
extern "C" void kernel_launch(void* const* d_in, const int* in_sizes, int n_in,
                              void* d_out, int out_size) {
    const float* atomic_num = (const float*)d_in[0];
    const float* coord      = (const float*)d_in[1];
    // d_in[2] = radius : dead (edge weight identically 1)
    const int*   src        = (const int*)d_in[3];
    const int*   dst        = (const int*)d_in[4];
    const int*   graph_id   = (const int*)d_in[5];
    const int*   abs_mask   = (const int*)d_in[6];
    const float* W_atom     = (const float*)d_in[7];
    const float* b_atom     = (const float*)d_in[8];
    const float* W_coord    = (const float*)d_in[9];
    const float* b_coord    = (const float*)d_in[10];
    const float* W_node     = (const float*)d_in[11];
    const float* b_node     = (const float*)d_in[12];
    // d_in[13] = exp_gnn : dead
    const float* eps_gnn    = (const float*)d_in[14];
    const float* W_mlp      = (const float*)d_in[15];
    const float* b_mlp      = (const float*)d_in[16];
    float* out = (float*)d_out;

    const int N = in_sizes[5];
    const int E = in_sizes[3];
    const int G = out_size / OUTD;

    kP<<<512, OUTD>>>(W_node, W_mlp);
    kWeff<<<KTOT, OUTD>>>(W_atom, W_coord, b_atom, b_coord, b_node, W_mlp);
    k_zero<<<(G * 128 + 255) / 256, 256>>>(G);
    k_hist<<<592, 256>>>(dst, graph_id, abs_mask, E, N, G);
    k_scan<<<1, 512>>>(G);
    k_scatter<<<592, 256>>>(src, dst, graph_id, abs_mask, E, N);
    k_accum<<<G * BPG, 256>>>(atomic_num, coord, eps_gnn);
    k_out<<<G, 128>>>(b_mlp, out, 1.f / (float)N);
}

// round 3
// speedup vs baseline: 2.4501x; 1.0456x over previous
#include <cuda_runtime.h>
#include <math.h>

#define OUTD   100
#define DDIM   256
#define ATOM   118
#define KTOT   122      // 118 atom + 3 coord + 1 constant (weight-sum feature)
#define MAXG   512
#define CAP    6144     // per-graph entry bucket capacity (max observed ~2.6k)
#define BPG    4        // blocks per graph in accumulate

// __device__ scratch (allocation-free rule)
__device__ float g_P[512 * OUTD];          // W_node @ W_mlp
__device__ float g_Weff[KTOT * OUTD];      // fused [A-features|const] -> logits
__device__ float g_M[MAXG * 128];          // per-graph weighted feature sums
__device__ int   g_cnt[MAXG];              // entries per graph
__device__ int   g_ent[MAXG * CAP];        // bucketed entries (sign bit => self-node)

// ---------------------------------------------------------------------------
// P[j][o] = sum_d W_node[j][d] * W_mlp[d][o]     (512 x 100)
// ---------------------------------------------------------------------------
__global__ void kP(const float* __restrict__ Wn, const float* __restrict__ Wm) {
    int j = blockIdx.x, o = threadIdx.x;
    float s = 0.f;
    #pragma unroll 4
    for (int d = 0; d < DDIM; d++) s += Wn[j * DDIM + d] * Wm[d * OUTD + o];
    g_P[j * OUTD + o] = s;
}

// ---------------------------------------------------------------------------
// W_eff rows: atom rows @ P_top, coord rows @ P_bot, last row = fused bias.
// ---------------------------------------------------------------------------
__global__ void kWeff(const float* __restrict__ Wa, const float* __restrict__ Wc,
                      const float* __restrict__ ba, const float* __restrict__ bc,
                      const float* __restrict__ bn, const float* __restrict__ Wm) {
    int k = blockIdx.x, o = threadIdx.x;
    float s = 0.f;
    if (k < ATOM) {
        #pragma unroll 4
        for (int m = 0; m < DDIM; m++) s += Wa[k * DDIM + m] * g_P[m * OUTD + o];
    } else if (k < 121) {
        #pragma unroll 4
        for (int m = 0; m < DDIM; m++) s += Wc[(k - ATOM) * DDIM + m] * g_P[(DDIM + m) * OUTD + o];
    } else {
        #pragma unroll 4
        for (int d = 0; d < DDIM; d++) s += bn[d] * Wm[d * OUTD + o];
        #pragma unroll 4
        for (int m = 0; m < DDIM; m++)
            s += ba[m] * g_P[m * OUTD + o] + bc[m] * g_P[(DDIM + m) * OUTD + o];
    }
    g_Weff[k * OUTD + o] = s;
}

// ---------------------------------------------------------------------------
__global__ void k_zero(int G) {
    int i = blockIdx.x * 256 + threadIdx.x;
    if (i < G * 128) g_M[i] = 0.f;
    if (i < G) g_cnt[i] = 0;
}

// ---------------------------------------------------------------------------
// Single-pass scatter into fixed-capacity per-graph buckets.
// Index space [0, E+N): i<E -> edge (target dst[i], payload src[i]);
//                       i>=E -> node self-entry (payload node | signbit).
// ---------------------------------------------------------------------------
__global__ void __launch_bounds__(256) k_scatter(const int* __restrict__ src,
                                                 const int* __restrict__ dst,
                                                 const int* __restrict__ gid,
                                                 const int* __restrict__ mask,
                                                 int E, int N) {
    int total = E + N;
    for (int i = blockIdx.x * 256 + threadIdx.x; i < total; i += gridDim.x * 256) {
        int tgt, payload;
        if (i < E) {
            tgt = __ldg(dst + i);
            payload = __ldg(src + i);
        } else {
            tgt = i - E;
            payload = tgt | 0x80000000;
        }
        if (__ldg(mask + tgt)) {
            int g = __ldg(gid + tgt);
            int p = atomicAdd(&g_cnt[g], 1);
            g_ent[g * CAP + p] = payload;
        }
    }
}

// ---------------------------------------------------------------------------
// M[g][k] = sum over entries of graph g:  w * A[node][k]
//   A[node] = [atomic_num(118) | coord(3) | 1.0], rows 8B-aligned -> float2.
// Lane l owns k = {2l, 2l+1} and {64+2l, 65+2l}; lanes 27-29 carry coords
// (k=118..120) in the second slot, lane 30 carries the constant (k=121).
// 32 warps per graph (BPG blocks x 8 warps), 4 entries per warp-iteration
// for deep MLP. Register accumulate -> smem reduce -> global atomic.
// ---------------------------------------------------------------------------
__global__ void __launch_bounds__(256) k_accum(const float* __restrict__ atom,
                                               const float* __restrict__ coord,
                                               const float* __restrict__ eps) {
    const int g    = blockIdx.x >> 2;          // BPG = 4
    const int part = blockIdx.x & 3;
    const int lane = threadIdx.x & 31;
    const int wwid = (part << 3) + (threadIdx.x >> 5);   // 0..31 within graph
    const int cnt  = g_cnt[g];
    const int* base = g_ent + (size_t)g * CAP;
    const float wn = 1.f + __ldg(eps);

    float2 a0 = make_float2(0.f, 0.f);
    float2 a1 = make_float2(0.f, 0.f);

    for (int i = wwid * 4; i < cnt; i += 128) {
        // Front-load the 4 entry ids (uniform across warp, L1/L2-hot).
        int ent[4]; bool val[4];
        #pragma unroll
        for (int j = 0; j < 4; j++) {
            val[j] = (i + j) < cnt;
            ent[j] = val[j] ? __ldg(base + i + j) : 0;
        }
        // Issue all gathers for the 4 entries, then accumulate.
        #pragma unroll
        for (int j = 0; j < 4; j++) {
            if (!val[j]) continue;
            int   node = ent[j] & 0x7FFFFFFF;
            float w    = (ent[j] < 0) ? wn : 1.f;
            const float2* r = (const float2*)(atom + (size_t)node * ATOM);
            float2 v0 = __ldg(r + lane);
            a0.x += w * v0.x; a0.y += w * v0.y;
            if (lane < 27) {
                float2 v1 = __ldg(r + 32 + lane);
                a1.x += w * v1.x; a1.y += w * v1.y;
            } else if (lane < 30) {
                a1.x += w * __ldg(coord + (size_t)node * 3 + (lane - 27));
            } else if (lane == 30) {
                a1.x += w;
            }
        }
    }

    __shared__ float red[128];
    if (threadIdx.x < 128) red[threadIdx.x] = 0.f;
    __syncthreads();
    atomicAdd(&red[2 * lane],     a0.x);
    atomicAdd(&red[2 * lane + 1], a0.y);
    if (lane < 27) {
        atomicAdd(&red[64 + 2 * lane],     a1.x);
        atomicAdd(&red[64 + 2 * lane + 1], a1.y);
    } else if (lane < 30) {
        atomicAdd(&red[118 + (lane - 27)], a1.x);
    } else if (lane == 30) {
        atomicAdd(&red[121], a1.x);
    }
    __syncthreads();
    if (threadIdx.x < KTOT) atomicAdd(&g_M[g * 128 + threadIdx.x], red[threadIdx.x]);
}

// ---------------------------------------------------------------------------
// out[g][o] = sigmoid( (M[g] @ W_eff)[o] / N + b_mlp[o] )
// ---------------------------------------------------------------------------
__global__ void __launch_bounds__(128) k_out(const float* __restrict__ bm,
                                             float* __restrict__ out, float invN) {
    __shared__ float sm[KTOT];
    int g = blockIdx.x, t = threadIdx.x;
    if (t < KTOT) sm[t] = g_M[g * 128 + t];
    __syncthreads();
    if (t < OUTD) {
        float z = 0.f;
        #pragma unroll 2
        for (int k = 0; k < KTOT; k++) z += sm[k] * g_Weff[k * OUTD + t];
        z = z * invN + bm[t];
        out[(size_t)g * OUTD + t] = 1.f / (1.f + __expf(-z));
    }
}

// ---------------------------------------------------------------------------
extern "C" void kernel_launch(void* const* d_in, const int* in_sizes, int n_in,
                              void* d_out, int out_size) {
    const float* atomic_num = (const float*)d_in[0];
    const float* coord      = (const float*)d_in[1];
    // d_in[2] = radius : dead (edge weight identically 1)
    const int*   src        = (const int*)d_in[3];
    const int*   dst        = (const int*)d_in[4];
    const int*   graph_id   = (const int*)d_in[5];
    const int*   abs_mask   = (const int*)d_in[6];
    const float* W_atom     = (const float*)d_in[7];
    const float* b_atom     = (const float*)d_in[8];
    const float* W_coord    = (const float*)d_in[9];
    const float* b_coord    = (const float*)d_in[10];
    const float* W_node     = (const float*)d_in[11];
    const float* b_node     = (const float*)d_in[12];
    // d_in[13] = exp_gnn : dead
    const float* eps_gnn    = (const float*)d_in[14];
    const float* W_mlp      = (const float*)d_in[15];
    const float* b_mlp      = (const float*)d_in[16];
    float* out = (float*)d_out;

    const int N = in_sizes[5];
    const int E = in_sizes[3];
    const int G = out_size / OUTD;

    kP<<<512, OUTD>>>(W_node, W_mlp);
    kWeff<<<KTOT, OUTD>>>(W_atom, W_coord, b_atom, b_coord, b_node, W_mlp);
    k_zero<<<(G * 128 + 255) / 256, 256>>>(G);
    k_scatter<<<1184, 256>>>(src, dst, graph_id, abs_mask, E, N);
    k_accum<<<G * BPG, 256>>>(atomic_num, coord, eps_gnn);
    k_out<<<G, 128>>>(b_mlp, out, 1.f / (float)N);
}

// round 4
// speedup vs baseline: 3.5513x; 1.4494x over previous
#include <cuda_runtime.h>
#include <math.h>

#define OUTD   100
#define DDIM   256
#define ATOM   118
#define KTOT   122      // 118 atom + 3 coord + 1 constant (weight-sum feature)
#define MAXG   512
#define CAP    6144     // per-graph bucket capacity (max expected ~2k)
#define BPG    4        // blocks per graph in accumulate
#define CHUNK  4096     // edges staged per scatter block

// __device__ scratch (allocation-free rule)
__device__ float g_P[512 * OUTD];          // W_node @ W_mlp
__device__ float g_Weff[KTOT * OUTD];      // fused [A-features|const] -> logits
__device__ float g_M[MAXG * 128];          // per-graph weighted feature sums
__device__ int   g_cnt[MAXG];              // entries per graph
__device__ int   g_mg[65536];              // fused mask/gid per node (-1 if masked out)
__device__ int   g_ent[MAXG * CAP];        // bucketed entries (sign bit => self-node)

// ---------------------------------------------------------------------------
// P[j][o] = sum_d W_node[j][d] * W_mlp[d][o]     (512 x 100)
// ---------------------------------------------------------------------------
__global__ void kP(const float* __restrict__ Wn, const float* __restrict__ Wm) {
    int j = blockIdx.x, o = threadIdx.x;
    float s = 0.f;
    #pragma unroll 4
    for (int d = 0; d < DDIM; d++) s += Wn[j * DDIM + d] * Wm[d * OUTD + o];
    g_P[j * OUTD + o] = s;
}

// ---------------------------------------------------------------------------
// W_eff rows: atom rows @ P_top, coord rows @ P_bot, last row = fused bias.
// ---------------------------------------------------------------------------
__global__ void kWeff(const float* __restrict__ Wa, const float* __restrict__ Wc,
                      const float* __restrict__ ba, const float* __restrict__ bc,
                      const float* __restrict__ bn, const float* __restrict__ Wm) {
    int k = blockIdx.x, o = threadIdx.x;
    float s = 0.f;
    if (k < ATOM) {
        #pragma unroll 4
        for (int m = 0; m < DDIM; m++) s += Wa[k * DDIM + m] * g_P[m * OUTD + o];
    } else if (k < 121) {
        #pragma unroll 4
        for (int m = 0; m < DDIM; m++) s += Wc[(k - ATOM) * DDIM + m] * g_P[(DDIM + m) * OUTD + o];
    } else {
        #pragma unroll 4
        for (int d = 0; d < DDIM; d++) s += bn[d] * Wm[d * OUTD + o];
        #pragma unroll 4
        for (int m = 0; m < DDIM; m++)
            s += ba[m] * g_P[m * OUTD + o] + bc[m] * g_P[(DDIM + m) * OUTD + o];
    }
    g_Weff[k * OUTD + o] = s;
}

// ---------------------------------------------------------------------------
// Zero M/cnt and build fused mg[n] = mask[n] ? gid[n] : -1
// ---------------------------------------------------------------------------
__global__ void k_init(const int* __restrict__ gid, const int* __restrict__ mask,
                       int N, int G) {
    int i = blockIdx.x * 256 + threadIdx.x;
    if (i < G * 128) g_M[i] = 0.f;
    if (i < G) g_cnt[i] = 0;
    if (i < N) g_mg[i] = __ldg(mask + i) ? __ldg(gid + i) : -1;
}

// ---------------------------------------------------------------------------
// Self-node entries (25k atomics, cheap)
// ---------------------------------------------------------------------------
__global__ void k_self(int N) {
    int n = blockIdx.x * 256 + threadIdx.x;
    if (n >= N) return;
    int g = g_mg[n];
    if (g >= 0) {
        int p = atomicAdd(&g_cnt[g], 1);
        g_ent[g * CAP + p] = n | (int)0x80000000;
    }
}

// ---------------------------------------------------------------------------
// Edge scatter with block-aggregated counter reservation.
// Stage CHUNK edges: smem histogram -> one global atomic per (block,graph)
// -> smem-cursor placement. Cuts global atomics ~4x and shortens the
// per-entry dependency chain to dst -> mg -> smem.
// ---------------------------------------------------------------------------
__global__ void __launch_bounds__(256) k_scatter(const int* __restrict__ src,
                                                 const int* __restrict__ dst,
                                                 int E, int G) {
    __shared__ int s_g[CHUNK];
    __shared__ int s_hist[MAXG];     // counts, then reused as cursors
    __shared__ int s_base[MAXG];
    const int t = threadIdx.x;
    const long e0 = (long)blockIdx.x * CHUNK;

    for (int g = t; g < G; g += 256) s_hist[g] = 0;
    __syncthreads();

    // Pass A: gather graph ids, histogram in smem
    #pragma unroll
    for (int j = 0; j < CHUNK / 256; j++) {
        long e = e0 + j * 256 + t;
        int g = -1;
        if (e < E) g = g_mg[__ldg(dst + e)];
        s_g[j * 256 + t] = g;
        if (g >= 0) atomicAdd(&s_hist[g], 1);
    }
    __syncthreads();

    // Pass B: reserve global ranges, one atomic per touched graph
    for (int g = t; g < G; g += 256) {
        int c = s_hist[g];
        s_base[g] = c ? atomicAdd(&g_cnt[g], c) : 0;
        s_hist[g] = 0;   // becomes cursor
    }
    __syncthreads();

    // Pass C: place entries via smem cursors
    #pragma unroll
    for (int j = 0; j < CHUNK / 256; j++) {
        long e = e0 + j * 256 + t;
        int g = s_g[j * 256 + t];
        if (g >= 0) {
            int p = s_base[g] + atomicAdd(&s_hist[g], 1);
            g_ent[g * CAP + p] = __ldg(src + e);
        }
    }
}

// ---------------------------------------------------------------------------
// M[g][k] = sum over entries of graph g:  w * A[node][k]
//   A[node] = [atomic_num(118) | coord(3) | 1.0], rows 8B-aligned -> float2.
// Lane l owns k={2l,2l+1} and {64+2l,65+2l}; lanes 27-29 carry coords,
// lane 30 the constant. 32 warps/graph (BPG blocks x 8 warps), 8 entries
// per warp-iter, branchless tail (weight 0) for deep MLP.
// ---------------------------------------------------------------------------
__global__ void __launch_bounds__(256) k_accum(const float* __restrict__ atom,
                                               const float* __restrict__ coord,
                                               const float* __restrict__ eps) {
    const int g    = blockIdx.x >> 2;          // BPG = 4
    const int part = blockIdx.x & 3;
    const int lane = threadIdx.x & 31;
    const int wwid = (part << 3) + (threadIdx.x >> 5);   // 0..31 within graph
    const int cnt  = g_cnt[g];
    const int* base = g_ent + (size_t)g * CAP;
    const float wn = 1.f + __ldg(eps);

    float2 a0 = make_float2(0.f, 0.f);
    float2 a1 = make_float2(0.f, 0.f);

    if (cnt > 0) {
        for (int i0 = wwid * 8; i0 < cnt; i0 += 256) {
            int ent[8]; float w[8];
            #pragma unroll
            for (int j = 0; j < 8; j++) {
                int idx = i0 + j;
                bool v = idx < cnt;
                int e = __ldg(base + (v ? idx : 0));
                w[j]   = v ? ((e < 0) ? wn : 1.f) : 0.f;
                ent[j] = e & 0x7FFFFFFF;
            }
            #pragma unroll
            for (int j = 0; j < 8; j++) {
                const float2* r = (const float2*)(atom + (size_t)ent[j] * ATOM);
                float2 v0 = __ldg(r + lane);
                a0.x += w[j] * v0.x; a0.y += w[j] * v0.y;
                if (lane < 27) {
                    float2 v1 = __ldg(r + 32 + lane);
                    a1.x += w[j] * v1.x; a1.y += w[j] * v1.y;
                } else if (lane < 30) {
                    a1.x += w[j] * __ldg(coord + (size_t)ent[j] * 3 + (lane - 27));
                } else if (lane == 30) {
                    a1.x += w[j];
                }
            }
        }
    }

    __shared__ float red[128];
    if (threadIdx.x < 128) red[threadIdx.x] = 0.f;
    __syncthreads();
    atomicAdd(&red[2 * lane],     a0.x);
    atomicAdd(&red[2 * lane + 1], a0.y);
    if (lane < 27) {
        atomicAdd(&red[64 + 2 * lane],     a1.x);
        atomicAdd(&red[64 + 2 * lane + 1], a1.y);
    } else if (lane < 30) {
        atomicAdd(&red[118 + (lane - 27)], a1.x);
    } else if (lane == 30) {
        atomicAdd(&red[121], a1.x);
    }
    __syncthreads();
    if (threadIdx.x < KTOT) atomicAdd(&g_M[g * 128 + threadIdx.x], red[threadIdx.x]);
}

// ---------------------------------------------------------------------------
// out[g][o] = sigmoid( (M[g] @ W_eff)[o] / N + b_mlp[o] )
// ---------------------------------------------------------------------------
__global__ void __launch_bounds__(128) k_out(const float* __restrict__ bm,
                                             float* __restrict__ out, float invN) {
    __shared__ float sm[KTOT];
    int g = blockIdx.x, t = threadIdx.x;
    if (t < KTOT) sm[t] = g_M[g * 128 + t];
    __syncthreads();
    if (t < OUTD) {
        float z = 0.f;
        #pragma unroll 2
        for (int k = 0; k < KTOT; k++) z += sm[k] * g_Weff[k * OUTD + t];
        z = z * invN + bm[t];
        out[(size_t)g * OUTD + t] = 1.f / (1.f + __expf(-z));
    }
}

// ---------------------------------------------------------------------------
extern "C" void kernel_launch(void* const* d_in, const int* in_sizes, int n_in,
                              void* d_out, int out_size) {
    const float* atomic_num = (const float*)d_in[0];
    const float* coord      = (const float*)d_in[1];
    // d_in[2] = radius : dead (edge weight identically 1)
    const int*   src        = (const int*)d_in[3];
    const int*   dst        = (const int*)d_in[4];
    const int*   graph_id   = (const int*)d_in[5];
    const int*   abs_mask   = (const int*)d_in[6];
    const float* W_atom     = (const float*)d_in[7];
    const float* b_atom     = (const float*)d_in[8];
    const float* W_coord    = (const float*)d_in[9];
    const float* b_coord    = (const float*)d_in[10];
    const float* W_node     = (const float*)d_in[11];
    const float* b_node     = (const float*)d_in[12];
    // d_in[13] = exp_gnn : dead
    const float* eps_gnn    = (const float*)d_in[14];
    const float* W_mlp      = (const float*)d_in[15];
    const float* b_mlp      = (const float*)d_in[16];
    float* out = (float*)d_out;

    const int N = in_sizes[5];
    const int E = in_sizes[3];
    const int G = out_size / OUTD;

    kP<<<512, OUTD>>>(W_node, W_mlp);
    kWeff<<<KTOT, OUTD>>>(W_atom, W_coord, b_atom, b_coord, b_node, W_mlp);
    k_init<<<(G * 128 + 255) / 256, 256>>>(graph_id, abs_mask, N, G);
    k_self<<<(N + 255) / 256, 256>>>(N);
    k_scatter<<<(int)((E + CHUNK - 1) / CHUNK), 256>>>(src, dst, E, G);
    k_accum<<<G * BPG, 256>>>(atomic_num, coord, eps_gnn);
    k_out<<<G, 128>>>(b_mlp, out, 1.f / (float)N);
}